// round 5
// baseline (speedup 1.0000x reference)
#include <cuda_runtime.h>

typedef unsigned long long ull;

#define BB 256
#define TT 2048
#define TB (TT * BB)

// layer-0 output: h1[t][b][64]  (fwd -> [0:32), bwd -> [32:64))
__device__ float g_h1[(size_t)TT * BB * 64];
// precomputed gate bases, INTERLEAVED: xg[dir][m][4*cell+gate], m = t*BB+b
__device__ float g_xg[(size_t)2 * TT * BB * 128];

__device__ __forceinline__ float sigf(float x) {
    return __fdividef(1.0f, 1.0f + __expf(-x));
}
__device__ __forceinline__ float tanh_fast(float x) {
    return 1.0f - __fdividef(2.0f, __expf(2.0f * x) + 1.0f);
}
__device__ __forceinline__ void unpack2(ull v, float& lo, float& hi) {
    asm("mov.b64 {%0, %1}, %2;" : "=f"(lo), "=f"(hi) : "l"(v));
}
__device__ __forceinline__ ull ffma2(ull a, ull b, ull c) {
    ull d;
    asm("fma.rn.f32x2 %0, %1, %2, %3;" : "=l"(d) : "l"(a), "l"(b), "l"(c));
    return d;
}
__device__ __forceinline__ ull fadd2(ull a, ull b) {
    ull d;
    asm("add.rn.f32x2 %0, %1, %2;" : "=l"(d) : "l"(a), "l"(b));
    return d;
}

// ---------------------------------------------------------------------------
// Precompute xg. 256 threads = 4 token-groups x 64 row-threads; each thread
// owns gate rows rq and rq+64 (weights in regs), so each broadcast LDS.128 of
// x feeds 4 ffma2. Output written interleaved: col = 4*cell + gate.
// ---------------------------------------------------------------------------
template<int F, bool L0>
__global__ __launch_bounds__(256)
void precompute(const float* __restrict__ oseq,  // [B,T,16] (L0 only)
                const float* __restrict__ iseq,  // [B,T,16] (L0 only)
                const float* __restrict__ Wih,   // [2,128,F]
                const float* __restrict__ bih,
                const float* __restrict__ bhh)
{
    constexpr int TM = 1024 / F;   // tokens per tile (TM*F = 1024 floats)
    constexpr int TG = TM / 4;     // tokens per group
    const int dir = blockIdx.y;
    const int tid = threadIdx.x;
    const int rq  = tid & 63;      // row pair: rq (i/f region), rq+64 (g/o)
    const int grp = tid >> 6;      // token group 0..3

    ull w0[F / 2], w1[F / 2];
    {
        const ull* p0 = (const ull*)(Wih + (size_t)(dir * 128 + rq) * F);
        const ull* p1 = (const ull*)(Wih + (size_t)(dir * 128 + rq + 64) * F);
        #pragma unroll
        for (int k = 0; k < F / 2; k++) { w0[k] = p0[k]; w1[k] = p1[k]; }
    }
    const float bias0 = bih[dir * 128 + rq] + bhh[dir * 128 + rq];
    const float bias1 = bih[dir * 128 + rq + 64] + bhh[dir * 128 + rq + 64];
    const int oc0 = ((rq & 31) << 2) | (rq >> 5);           // 4*cell + gate
    const int oc1 = ((rq & 31) << 2) | ((rq >> 5) + 2);

    __shared__ __align__(16) float x_sh[2][TM][F];

    const int stride = gridDim.x * TM;
    const int srow = tid / (F / 4);
    const int sseg = tid % (F / 4);

    auto stage = [&](int m0, int buf) {
        const int m = m0 + srow;
        float4 v;
        if (L0) {
            const int t = m >> 8, bb = m & 255;
            if (sseg < 4) v = *(const float4*)&oseq[((size_t)bb * TT + t) * 16 + sseg * 4];
            else          v = *(const float4*)&iseq[((size_t)bb * TT + (TT - 1 - t)) * 16 + (sseg - 4) * 4];
        } else {
            v = *(const float4*)&g_h1[(size_t)m * 64 + sseg * 4];
        }
        *(float4*)&x_sh[buf][srow][sseg * 4] = v;
    };

    int buf = 0;
    int m0 = blockIdx.x * TM;
    if (m0 < TB) stage(m0, 0);

    float* const xg = g_xg + (size_t)dir * TB * 128;

    for (; m0 < TB; m0 += stride) {
        __syncthreads();
        const int mn = m0 + stride;
        if (mn < TB) stage(mn, buf ^ 1);

        ull a0[TG], a1[TG];
        #pragma unroll
        for (int i = 0; i < TG; i++) { a0[i] = 0ull; a1[i] = 0ull; }

        const ulonglong2* xp = (const ulonglong2*)&x_sh[buf][grp * TG][0];
        #pragma unroll
        for (int j = 0; j < F / 4; j++) {
            #pragma unroll
            for (int i = 0; i < TG; i++) {
                const ulonglong2 v = xp[i * (F / 4) + j];
                a0[i] = ffma2(w0[2 * j],     v.x, a0[i]);
                a0[i] = ffma2(w0[2 * j + 1], v.y, a0[i]);
                a1[i] = ffma2(w1[2 * j],     v.x, a1[i]);
                a1[i] = ffma2(w1[2 * j + 1], v.y, a1[i]);
            }
        }

        #pragma unroll
        for (int i = 0; i < TG; i++) {
            float lo, hi;
            const size_t mrow = (size_t)(m0 + grp * TG + i) * 128;
            unpack2(a0[i], lo, hi);
            xg[mrow + oc0] = (lo + hi) + bias0;
            unpack2(a1[i], lo, hi);
            xg[mrow + oc1] = (lo + hi) + bias1;
        }
        buf ^= 1;
    }
}

// ---------------------------------------------------------------------------
// Recurrent: each warp owns TWO same-direction batches (shared W_hh regs);
// the two independent chains interleave so issue work of one hides latency
// of the other. Lane l owns cell l (gate rows l, 32+l, 64+l, 96+l).
// xg read as one coalesced LDG.128 per batch-step (interleaved layout),
// prefetched 4 steps ahead. h exchange: single-buffer smem + 1 syncwarp/step.
// ---------------------------------------------------------------------------
template<bool L0K>
__global__ __launch_bounds__(128)
void recurrent(const float* __restrict__ Whh,   // [2,128,32]
               float* __restrict__ outp)        // L1: d_out [B,T,64]
{
    const int dir  = blockIdx.y;
    const int warp = threadIdx.x >> 5;
    const int lane = threadIdx.x & 31;
    const int bA   = blockIdx.x * 8 + warp * 2;
    const int bB   = bA + 1;

    ull w[4][16];
    #pragma unroll
    for (int g = 0; g < 4; g++) {
        const ull* p = (const ull*)(Whh + (size_t)(dir * 128 + g * 32 + lane) * 32);
        #pragma unroll
        for (int k = 0; k < 16; k++) w[g][k] = p[k];
    }

    __shared__ __align__(16) float h_sh[4][2][32];
    h_sh[warp][0][lane] = 0.0f;
    h_sh[warp][1][lane] = 0.0f;
    float cA = 0.0f, cB = 0.0f;
    __syncwarp();

    const size_t t0off = (size_t)(dir ? (TT - 1) * BB : 0);
    const float* xA = g_xg + ((size_t)dir * TB + t0off + bA) * 128 + lane * 4;
    const float* xB = g_xg + ((size_t)dir * TB + t0off + bB) * 128 + lane * 4;
    const long long stp = (dir ? -(long long)BB : (long long)BB) * 128;

    float4 fA[4], fB[4];
    #pragma unroll
    for (int d = 0; d < 4; d++) {
        fA[d] = *(const float4*)(xA + (long long)d * stp);
        fB[d] = *(const float4*)(xB + (long long)d * stp);
    }

    auto reduce = [&](const float* hbuf, float4 xg4, float& gi, float& gf,
                      float& gg, float& go) {
        const ulonglong2* hp = (const ulonglong2*)hbuf;
        ull aA0 = 0, aB0 = 0, aA1 = 0, aB1 = 0, aA2 = 0, aB2 = 0, aA3 = 0, aB3 = 0;
        #pragma unroll
        for (int k = 0; k < 8; k++) {
            const ulonglong2 hv = hp[k];
            aA0 = ffma2(w[0][2 * k], hv.x, aA0); aB0 = ffma2(w[0][2 * k + 1], hv.y, aB0);
            aA1 = ffma2(w[1][2 * k], hv.x, aA1); aB1 = ffma2(w[1][2 * k + 1], hv.y, aB1);
            aA2 = ffma2(w[2][2 * k], hv.x, aA2); aB2 = ffma2(w[2][2 * k + 1], hv.y, aB2);
            aA3 = ffma2(w[3][2 * k], hv.x, aA3); aB3 = ffma2(w[3][2 * k + 1], hv.y, aB3);
        }
        float lo, hi;
        ull s0 = fadd2(aA0, aB0); unpack2(s0, lo, hi); gi = xg4.x + (lo + hi);
        ull s1 = fadd2(aA1, aB1); unpack2(s1, lo, hi); gf = xg4.y + (lo + hi);
        ull s2 = fadd2(aA2, aB2); unpack2(s2, lo, hi); gg = xg4.z + (lo + hi);
        ull s3 = fadd2(aA3, aB3); unpack2(s3, lo, hi); go = xg4.w + (lo + hi);
    };

    auto cell = [&](float gi, float gf, float gg, float go, float& c) -> float {
        const float fi = sigf(gi);
        const float ff = sigf(gf);
        const float tg = tanh_fast(gg);
        const float fo = sigf(go);
        c = fmaf(ff, c, fi * tg);
        return fo * tanh_fast(c);
    };

    for (int s = 0; s < TT; s += 4) {
        #pragma unroll
        for (int d = 0; d < 4; d++) {
            const int ss = s + d;
            const float4 gA4 = fA[d], gB4 = fB[d];
            if (ss + 4 < TT) {
                fA[d] = *(const float4*)(xA + (long long)(ss + 4) * stp);
                fB[d] = *(const float4*)(xB + (long long)(ss + 4) * stp);
            }

            float giA, gfA, ggA, goA, giB, gfB, ggB, goB;
            reduce(h_sh[warp][0], gA4, giA, gfA, ggA, goA);
            reduce(h_sh[warp][1], gB4, giB, gfB, ggB, goB);

            const float hA = cell(giA, gfA, ggA, goA, cA);
            const float hB = cell(giB, gfB, ggB, goB, cB);

            h_sh[warp][0][lane] = hA;
            h_sh[warp][1][lane] = hB;
            __syncwarp();

            const int t = dir ? (TT - 1 - ss) : ss;
            if (L0K) {
                g_h1[((size_t)t * BB + bA) * 64 + dir * 32 + lane] = hA;
                g_h1[((size_t)t * BB + bB) * 64 + dir * 32 + lane] = hB;
            } else {
                outp[((size_t)bA * TT + t) * 64 + dir * 32 + lane] = hA;
                outp[((size_t)bB * TT + t) * 64 + dir * 32 + lane] = hB;
            }
        }
    }
}

extern "C" void kernel_launch(void* const* d_in, const int* in_sizes, int n_in,
                              void* d_out, int out_size) {
    (void)in_sizes; (void)n_in; (void)out_size;
    const float* oseq = (const float*)d_in[0];
    const float* iseq = (const float*)d_in[1];
    const float* Wih0 = (const float*)d_in[2];
    const float* Whh0 = (const float*)d_in[3];
    const float* bih0 = (const float*)d_in[4];
    const float* bhh0 = (const float*)d_in[5];
    const float* Wih1 = (const float*)d_in[6];
    const float* Whh1 = (const float*)d_in[7];
    const float* bih1 = (const float*)d_in[8];
    const float* bhh1 = (const float*)d_in[9];
    float* out = (float*)d_out;

    precompute<32, true ><<<dim3(148, 2), 256>>>(oseq, iseq, Wih0, bih0, bhh0);
    recurrent<true ><<<dim3(32, 2), 128>>>(Whh0, nullptr);
    precompute<64, false><<<dim3(148, 2), 256>>>(nullptr, nullptr, Wih1, bih1, bhh1);
    recurrent<false><<<dim3(32, 2), 128>>>(Whh1, out);
}

// round 6
// speedup vs baseline: 1.1739x; 1.1739x over previous
#include <cuda_runtime.h>

typedef unsigned long long ull;

#define BB 256
#define TT 2048
#define TB (TT * BB)

// b-major everywhere: token m = b*TT + t
// layer-0 output: g_h1[(b*TT + t)*64 + dir*32 + cell]
__device__ float g_h1[(size_t)TB * 64];
// gate bases: g_xg[((dir*BB + b)*TT + t)*128 + col]
// col = half*64 + 2*cell + q : half0 -> {i,f} pair, half1 -> {g,o} pair
__device__ float g_xg[(size_t)2 * TB * 128];

__device__ __forceinline__ float sigf(float x) {
    return __fdividef(1.0f, 1.0f + __expf(-x));
}
__device__ __forceinline__ float tanh_fast(float x) {
    return 1.0f - __fdividef(2.0f, __expf(2.0f * x) + 1.0f);
}
__device__ __forceinline__ ull pack2(float lo, float hi) {
    ull r;
    asm("mov.b64 %0, {%1, %2};" : "=l"(r) : "f"(lo), "f"(hi));
    return r;
}
__device__ __forceinline__ void unpack2(ull v, float& lo, float& hi) {
    asm("mov.b64 {%0, %1}, %2;" : "=f"(lo), "=f"(hi) : "l"(v));
}
__device__ __forceinline__ ull ffma2(ull a, ull b, ull c) {
    ull d;
    asm("fma.rn.f32x2 %0, %1, %2, %3;" : "=l"(d) : "l"(a), "l"(b), "l"(c));
    return d;
}
__device__ __forceinline__ ull fadd2(ull a, ull b) {
    ull d;
    asm("add.rn.f32x2 %0, %1, %2;" : "=l"(d) : "l"(a), "l"(b));
    return d;
}

// ---------------------------------------------------------------------------
// Precompute xg. 256 threads = 4 token-groups x 64 row-threads. Thread rq
// owns rows (half*64+cell) and (half*64+32+cell)  [half=rq>>5, cell=rq&31],
// i.e. an {i,f} or {g,o} pair for one cell -> one dense STG.64 per token.
// b-major m => L0 stage loads fully coalesced.
// ---------------------------------------------------------------------------
template<int F, bool L0>
__global__ __launch_bounds__(256)
void precompute(const float* __restrict__ oseq,  // [B,T,16] (L0 only)
                const float* __restrict__ iseq,  // [B,T,16] (L0 only)
                const float* __restrict__ Wih,   // [2,128,F]
                const float* __restrict__ bih,
                const float* __restrict__ bhh)
{
    constexpr int TM = 1024 / F;   // tokens per tile
    constexpr int TG = TM / 4;     // tokens per group
    const int dir  = blockIdx.y;
    const int tid  = threadIdx.x;
    const int rq   = tid & 63;
    const int grp  = tid >> 6;
    const int half = rq >> 5;
    const int cell = rq & 31;
    const int row0 = half * 64 + cell;        // i or g row
    const int row1 = half * 64 + 32 + cell;   // f or o row

    ull w0[F / 2], w1[F / 2];
    {
        const ull* p0 = (const ull*)(Wih + (size_t)(dir * 128 + row0) * F);
        const ull* p1 = (const ull*)(Wih + (size_t)(dir * 128 + row1) * F);
        #pragma unroll
        for (int k = 0; k < F / 2; k++) { w0[k] = p0[k]; w1[k] = p1[k]; }
    }
    const float bias0 = bih[dir * 128 + row0] + bhh[dir * 128 + row0];
    const float bias1 = bih[dir * 128 + row1] + bhh[dir * 128 + row1];
    const int ocol = half * 64 + 2 * cell;

    __shared__ __align__(16) float x_sh[2][TM][F];

    const int stride = gridDim.x * TM;
    const int srow = tid / (F / 4);
    const int sseg = tid % (F / 4);

    auto stage = [&](int m0, int buf) {
        const int m = m0 + srow;
        const int t = m & (TT - 1);
        const int bb = m >> 11;
        float4 v;
        if (L0) {
            if (sseg < 4) v = *(const float4*)&oseq[((size_t)bb * TT + t) * 16 + sseg * 4];
            else          v = *(const float4*)&iseq[((size_t)bb * TT + (TT - 1 - t)) * 16 + (sseg - 4) * 4];
        } else {
            v = *(const float4*)&g_h1[(size_t)m * 64 + sseg * 4];
        }
        *(float4*)&x_sh[buf][srow][sseg * 4] = v;
    };

    int buf = 0;
    int m0 = blockIdx.x * TM;
    if (m0 < TB) stage(m0, 0);

    float* const xg = g_xg + (size_t)dir * TB * 128;

    for (; m0 < TB; m0 += stride) {
        __syncthreads();
        const int mn = m0 + stride;
        if (mn < TB) stage(mn, buf ^ 1);

        ull a0[TG], a1[TG];
        #pragma unroll
        for (int i = 0; i < TG; i++) { a0[i] = 0ull; a1[i] = 0ull; }

        const ulonglong2* xp = (const ulonglong2*)&x_sh[buf][grp * TG][0];
        #pragma unroll
        for (int j = 0; j < F / 4; j++) {
            #pragma unroll
            for (int i = 0; i < TG; i++) {
                const ulonglong2 v = xp[i * (F / 4) + j];
                a0[i] = ffma2(w0[2 * j],     v.x, a0[i]);
                a0[i] = ffma2(w0[2 * j + 1], v.y, a0[i]);
                a1[i] = ffma2(w1[2 * j],     v.x, a1[i]);
                a1[i] = ffma2(w1[2 * j + 1], v.y, a1[i]);
            }
        }

        #pragma unroll
        for (int i = 0; i < TG; i++) {
            float lo, hi;
            float2 o;
            unpack2(a0[i], lo, hi);
            o.x = (lo + hi) + bias0;
            unpack2(a1[i], lo, hi);
            o.y = (lo + hi) + bias1;
            *(float2*)&xg[(size_t)(m0 + grp * TG + i) * 128 + ocol] = o;
        }
        buf ^= 1;
    }
}

// ---------------------------------------------------------------------------
// Recurrent: ONE chain per 64-thread block (2 warps). Warp0 owns gate rows
// {i,f}, warp1 owns {g,o}; each warp does 32 ffma2/step. Warp1's tanh(g)/
// sig(o) run in parallel with warp0's sigmoids; exchange via smem + cheap
// 2-warp __syncthreads. xg: one coalesced LDG.64/warp/step, prefetched 4 deep,
// folded into accumulator init.
// ---------------------------------------------------------------------------
template<bool L0K>
__global__ __launch_bounds__(64)
void recurrent(const float* __restrict__ Whh,   // [2,128,32]
               float* __restrict__ outp)        // L1: d_out [B,T,64]
{
    const int dir  = blockIdx.y;
    const int bb   = blockIdx.x;
    const int wp   = threadIdx.x >> 5;   // 0: i,f   1: g,o
    const int lane = threadIdx.x & 31;

    const int row0 = wp * 64 + lane;        // i or g
    const int row1 = wp * 64 + 32 + lane;   // f or o

    ull w0[16], w1[16];
    {
        const ull* p0 = (const ull*)(Whh + (size_t)(dir * 128 + row0) * 32);
        const ull* p1 = (const ull*)(Whh + (size_t)(dir * 128 + row1) * 32);
        #pragma unroll
        for (int k = 0; k < 16; k++) { w0[k] = p0[k]; w1[k] = p1[k]; }
    }

    __shared__ __align__(16) float h_sh[32];
    __shared__ float ex_tg[32], ex_so[32];
    if (threadIdx.x < 32) h_sh[threadIdx.x] = 0.0f;
    float c = 0.0f;
    __syncthreads();

    float* const hout = L0K ? g_h1 : outp;

    const float* xbase = g_xg + ((size_t)(dir * BB + bb) * TT + (dir ? TT - 1 : 0)) * 128
                       + wp * 64 + 2 * lane;
    const long long stp = dir ? -128 : 128;

    float2 xf[4];
    #pragma unroll
    for (int d = 0; d < 4; d++)
        xf[d] = *(const float2*)(xbase + (long long)d * stp);

    for (int s = 0; s < TT; s += 4) {
        #pragma unroll
        for (int d = 0; d < 4; d++) {
            const int ss = s + d;
            const float2 xg2 = xf[d];
            if (ss + 4 < TT)
                xf[d] = *(const float2*)(xbase + (long long)(ss + 4) * stp);

            // reduce: gate0 = row0 . h, gate1 = row1 . h  (xg folded into init)
            ull a0 = pack2(xg2.x, 0.0f), b0 = 0ull;
            ull a1 = pack2(xg2.y, 0.0f), b1 = 0ull;
            const ulonglong2* hp = (const ulonglong2*)h_sh;
            #pragma unroll
            for (int k = 0; k < 8; k++) {
                const ulonglong2 hv = hp[k];
                a0 = ffma2(w0[2 * k],     hv.x, a0);
                b0 = ffma2(w0[2 * k + 1], hv.y, b0);
                a1 = ffma2(w1[2 * k],     hv.x, a1);
                b1 = ffma2(w1[2 * k + 1], hv.y, b1);
            }
            float lo, hi, g0, g1;
            ull s0 = fadd2(a0, b0); unpack2(s0, lo, hi); g0 = lo + hi;
            ull s1 = fadd2(a1, b1); unpack2(s1, lo, hi); g1 = lo + hi;

            float si = 0.0f, sf = 0.0f;
            if (wp == 1) {
                ex_tg[lane] = tanh_fast(g0);   // tanh(g)
                ex_so[lane] = sigf(g1);        // sig(o)
            } else {
                si = sigf(g0);                 // sig(i)
                sf = sigf(g1);                 // sig(f)
            }
            __syncthreads();

            if (wp == 0) {
                const float tg = ex_tg[lane];
                const float so = ex_so[lane];
                c = fmaf(sf, c, si * tg);
                const float h = so * tanh_fast(c);
                h_sh[lane] = h;
                const int t = dir ? (TT - 1 - ss) : ss;
                hout[((size_t)bb * TT + t) * 64 + dir * 32 + lane] = h;
            }
            __syncthreads();
        }
    }
}

extern "C" void kernel_launch(void* const* d_in, const int* in_sizes, int n_in,
                              void* d_out, int out_size) {
    (void)in_sizes; (void)n_in; (void)out_size;
    const float* oseq = (const float*)d_in[0];
    const float* iseq = (const float*)d_in[1];
    const float* Wih0 = (const float*)d_in[2];
    const float* Whh0 = (const float*)d_in[3];
    const float* bih0 = (const float*)d_in[4];
    const float* bhh0 = (const float*)d_in[5];
    const float* Wih1 = (const float*)d_in[6];
    const float* Whh1 = (const float*)d_in[7];
    const float* bih1 = (const float*)d_in[8];
    const float* bhh1 = (const float*)d_in[9];
    float* out = (float*)d_out;

    precompute<32, true ><<<dim3(148, 2), 256>>>(oseq, iseq, Wih0, bih0, bhh0);
    recurrent<true ><<<dim3(BB, 2), 64>>>(Whh0, nullptr);
    precompute<64, false><<<dim3(148, 2), 256>>>(nullptr, nullptr, Wih1, bih1, bhh1);
    recurrent<false><<<dim3(BB, 2), 64>>>(Whh1, out);
}